// round 15
// baseline (speedup 1.0000x reference)
#include <cuda_runtime.h>
#include <math.h>

#define N      8192
#define D      64
#define DA     65          // table row: 64 h-dims + 1 Z column
#define NB     4096        // buckets
#define ALPHA  0.2f
#define RPB    32          // rows per block in k_hf (4 rows per thread)
#define NCHUNK 64          // chunks for table scan
#define CB     (NB / NCHUNK)  // 64 buckets per chunk
#define RLO   (-10.0f)
#define RHI   (10.0f)

// ---------------- scratch (device globals; no allocation allowed) -------------
__device__ __align__(16) float g_h[N * D];
__device__ float g_f1[N];
__device__ float g_f2[N];
__device__ int   g_cnt[NB];
__device__ int   g_start[NB + 1];
__device__ int   g_ord[N];
__device__ float g_f2s[N];
__device__ __align__(16) float g_accP[NB * D];   // per-bucket sums of e^{f2} * h
__device__ __align__(16) float g_accN[NB * D];   // per-bucket sums of e^{a f2} * h
__device__ float g_accPZ[NB];            // per-bucket sums of e^{f2}
__device__ float g_accNZ[NB];            // per-bucket sums of e^{a f2}
__device__ float g_tp[(NB + 1) * DA];    // suffix sums over buckets (row NB stays 0)
__device__ float g_tn[NB * DA];          // exclusive prefix sums over buckets
__device__ float g_csP[NCHUNK][DA];      // per-chunk totals (index 64 = Z)
__device__ float g_csN[NCHUNK][DA];
__device__ int   g_arrived;              // single-pass scan barrier (self-resetting)
__device__ int   g_done;

__device__ __forceinline__ int bucket_of(float v) {
    float t = (v - RLO) * ((float)NB / (RHI - RLO));
    int b = (int)t;               // truncation; monotone non-decreasing in v
    if (b < 0) b = 0;
    if (b > NB - 1) b = NB - 1;
    return b;
}

__device__ __forceinline__ void red_add_v4(float* p, float a, float b, float c, float d) {
    asm volatile("red.global.add.v4.f32 [%0], {%1, %2, %3, %4};"
                 :: "l"(p), "f"(a), "f"(b), "f"(c), "f"(d) : "memory");
}

// ------- 1: h = x @ Wt (32-row tiles, 4 rows x 4 dims per thread); f1,f2;
//            histogram + bucket accumulation via vector atomics ---------------
// 128 threads/block: og = tid&15 (dim group), rg = tid>>4 (row group of 4).
// W smem reads amortized over 4 rows -> 32 LDS.128 per row (crossbar-bound fix).
__global__ void __launch_bounds__(128) k_hf(
    const float* __restrict__ x, const float* __restrict__ Wt,
    const float* __restrict__ a1, const float* __restrict__ b1,
    const float* __restrict__ a2, const float* __restrict__ b2) {
    __shared__ __align__(16) float sW[D * D];      // W[i][o], 16KB
    __shared__ __align__(16) float sx[RPB * D];    // x[r][i], 8KB
    int tid = threadIdx.x;
    int row0 = blockIdx.x * RPB;
    {
        const float4* wsrc = (const float4*)Wt;
        const float4* xsrc = (const float4*)(x + row0 * D);
#pragma unroll
        for (int it = 0; it < 8; it++) ((float4*)sW)[tid + 128 * it] = wsrc[tid + 128 * it];
#pragma unroll
        for (int it = 0; it < 4; it++) ((float4*)sx)[tid + 128 * it] = xsrc[tid + 128 * it];
    }
    __syncthreads();

    int og = tid & 15;              // dims og*4 .. og*4+3
    int rg = tid >> 4;              // rows rg*4 .. rg*4+3
    float acc[4][4];
#pragma unroll
    for (int q = 0; q < 4; q++)
#pragma unroll
        for (int c = 0; c < 4; c++) acc[q][c] = 0.0f;

#pragma unroll 4
    for (int i4 = 0; i4 < 16; i4++) {
        float4 xv[4];
#pragma unroll
        for (int q = 0; q < 4; q++) xv[q] = ((const float4*)sx)[(rg * 4 + q) * 16 + i4];
        float xk[4][4];
#pragma unroll
        for (int q = 0; q < 4; q++) {
            xk[q][0] = xv[q].x; xk[q][1] = xv[q].y; xk[q][2] = xv[q].z; xk[q][3] = xv[q].w;
        }
#pragma unroll
        for (int k = 0; k < 4; k++) {
            float4 wv = ((const float4*)sW)[(i4 * 4 + k) * 16 + og];
#pragma unroll
            for (int q = 0; q < 4; q++) {
                acc[q][0] = fmaf(xk[q][k], wv.x, acc[q][0]);
                acc[q][1] = fmaf(xk[q][k], wv.y, acc[q][1]);
                acc[q][2] = fmaf(xk[q][k], wv.z, acc[q][2]);
                acc[q][3] = fmaf(xk[q][k], wv.w, acc[q][3]);
            }
        }
    }
    // store h
#pragma unroll
    for (int q = 0; q < 4; q++) {
        ((float4*)g_h)[(row0 + rg * 4 + q) * 16 + og] =
            make_float4(acc[q][0], acc[q][1], acc[q][2], acc[q][3]);
    }
    // scores: butterfly over the 16 og-lanes -> every lane holds full sums
    float4 A1 = ((const float4*)a1)[og];
    float4 A2 = ((const float4*)a2)[og];
    float p1[4], p2[4];
#pragma unroll
    for (int q = 0; q < 4; q++) {
        p1[q] = acc[q][0] * A1.x + acc[q][1] * A1.y + acc[q][2] * A1.z + acc[q][3] * A1.w;
        p2[q] = acc[q][0] * A2.x + acc[q][1] * A2.y + acc[q][2] * A2.z + acc[q][3] * A2.w;
    }
#pragma unroll
    for (int s = 8; s > 0; s >>= 1) {
#pragma unroll
        for (int q = 0; q < 4; q++) {
            p1[q] += __shfl_xor_sync(0xffffffffu, p1[q], s);
            p2[q] += __shfl_xor_sync(0xffffffffu, p2[q], s);
        }
    }
    float b1v = b1[0], b2v = b2[0];
#pragma unroll
    for (int q = 0; q < 4; q++) {
        float f2v = p2[q] + b2v;
        float ep = __expf(f2v);
        float en = __expf(ALPHA * f2v);
        int b = bucket_of(f2v);
        red_add_v4(&g_accP[b * D + og * 4],
                   ep * acc[q][0], ep * acc[q][1], ep * acc[q][2], ep * acc[q][3]);
        red_add_v4(&g_accN[b * D + og * 4],
                   en * acc[q][0], en * acc[q][1], en * acc[q][2], en * acc[q][3]);
        if (og == 0) {
            int row = row0 + rg * 4 + q;
            g_f1[row] = p1[q] + b1v;
            g_f2[row] = f2v;
            atomicAdd(&g_accPZ[b], ep);
            atomicAdd(&g_accNZ[b], en);
            atomicAdd(&g_cnt[b], 1);
        }
    }
}

// ------- 2: merged mid-kernel, 65 blocks x 256 threads ------------------------
// Blocks 0..63: chunked scan of acc arrays -> suffix/prefix tables
//               (device-wide arrive barrier among the 64 table blocks only).
// Block 64:     scan of bucket counts + counting-sort placement (independent).
// Both paths are self-cleaning for the next graph replay.
__global__ void __launch_bounds__(256) k_mid() {
    __shared__ __align__(16) float s_buf[8200];      // 32.8KB, aliased by both paths
    __shared__ float sPZ[CB], sNZ[CB];
    int t = threadIdx.x;

    if (blockIdx.x == NCHUNK) {
        // -------- scanplace path --------
        int* sstart = (int*)s_buf;            // NB+1 ints
        int* scur   = (int*)s_buf + NB + 1;   // NB ints
        __shared__ int wsum[8];
        int v[16];
        int tot = 0;
#pragma unroll
        for (int g = 0; g < 4; g++) {
            int4 c4 = *(const int4*)&g_cnt[t * 16 + g * 4];
            *(int4*)&g_cnt[t * 16 + g * 4] = make_int4(0, 0, 0, 0);  // reset
            v[g * 4 + 0] = c4.x; v[g * 4 + 1] = c4.y;
            v[g * 4 + 2] = c4.z; v[g * 4 + 3] = c4.w;
            tot += c4.x + c4.y + c4.z + c4.w;
        }
        int lane = t & 31, w = t >> 5;
        int inc = tot;
#pragma unroll
        for (int s = 1; s < 32; s <<= 1) {
            int tv = __shfl_up_sync(0xffffffffu, inc, s);
            if (lane >= s) inc += tv;
        }
        if (lane == 31) wsum[w] = inc;
        __syncthreads();
        if (w == 0 && lane < 8) {
            int u = wsum[lane];
#pragma unroll
            for (int s = 1; s < 8; s <<= 1) {
                int tv = __shfl_up_sync(0x000000ffu, u, s);
                if (lane >= s) u += tv;
            }
            wsum[lane] = u;
        }
        __syncthreads();
        int run = inc - tot + (w > 0 ? wsum[w - 1] : 0);
#pragma unroll
        for (int k = 0; k < 16; k++) {
            int b = t * 16 + k;
            sstart[b] = run;
            g_start[b] = run;
            scur[b] = 0;
            run += v[k];
        }
        if (t == 255) { sstart[NB] = run; g_start[NB] = run; }
        __syncthreads();
#pragma unroll
        for (int k = 0; k < N / 256; k++) {
            int j = k * 256 + t;
            float f = g_f2[j];
            int b = bucket_of(f);
            int pos = sstart[b] + atomicAdd(&scur[b], 1);
            g_ord[pos] = j;
            g_f2s[pos] = f;
        }
        return;
    }

    // -------- tables path: one 64-bucket chunk per block --------
    float* sP = s_buf;                   // CB*64 floats
    float* sN = s_buf + CB * D;          // CB*64 floats
    int c = blockIdx.x;
    const int CHF4 = CB * D / 4;         // 1024 float4 per chunk per array
    const float4* aP = (const float4*)&g_accP[c * CB * D];
    const float4* aN = (const float4*)&g_accN[c * CB * D];
    for (int i = t; i < CHF4; i += 256) {
        ((float4*)sP)[i] = aP[i];
        ((float4*)sN)[i] = aN[i];
    }
    if (t < CB) {
        sPZ[t] = g_accPZ[c * CB + t];
        sNZ[t] = g_accNZ[c * CB + t];
        g_accPZ[c * CB + t] = 0.0f;      // reset for next call
        g_accNZ[c * CB + t] = 0.0f;
    }
    __syncthreads();

    if (t < D) {
        float sumP = 0.0f, sumN = 0.0f;
#pragma unroll 4
        for (int b = 0; b < CB; b++) {
            sumP += sP[b * D + t];
            sumN += sN[b * D + t];
        }
        g_csP[c][t] = sumP;
        g_csN[c][t] = sumN;
    } else if (t == D) {
        float zP = 0.0f, zN = 0.0f;
#pragma unroll 4
        for (int b = 0; b < CB; b++) { zP += sPZ[b]; zN += sNZ[b]; }
        g_csP[c][64] = zP;
        g_csN[c][64] = zN;
    }
    float4 z4 = make_float4(0.f, 0.f, 0.f, 0.f);
    for (int i = t; i < CHF4; i += 256) {      // zero own chunk for next call
        ((float4*)&g_accP[c * CB * D])[i] = z4;
        ((float4*)&g_accN[c * CB * D])[i] = z4;
    }
    __threadfence();
    __syncthreads();
    if (t == 0) {
        atomicAdd(&g_arrived, 1);
        while (atomicAdd(&g_arrived, 0) < NCHUNK) { }
    }
    __syncthreads();

    if (t < DA) {
        float offP = 0.0f, offN = 0.0f;
        for (int cc = c + 1; cc < NCHUNK; cc++) offP += g_csP[cc][t];
        for (int cc = 0; cc < c; cc++)          offN += g_csN[cc][t];
        float runP = offP;
        for (int b = CB - 1; b >= 0; b--) {        // inclusive suffix
            float vP = (t < D) ? sP[b * D + t] : sPZ[b];
            runP += vP;
            g_tp[(c * CB + b) * DA + t] = runP;
        }
        float runN = offN;
        for (int b = 0; b < CB; b++) {             // exclusive prefix
            float vN = (t < D) ? sN[b * D + t] : sNZ[b];
            g_tn[(c * CB + b) * DA + t] = runN;
            runN += vN;
        }
    }
    __syncthreads();
    if (t == 0) {
        int dd = atomicAdd(&g_done, 1);
        if (dd == NCHUNK - 1) { g_arrived = 0; g_done = 0; }
    }
}

// ---------------- 3: per-row query + residual (4-way unrolled) + ELU ---------
__global__ void __launch_bounds__(256) k_out(float* __restrict__ out) {
    __shared__ float s_c[4][64];
    __shared__ int   s_j[4][64];
    __shared__ float s_w[4], s_inv[4], s_thr[4];
    __shared__ int   s_p0[4], s_p1[4], s_b[4];
    __shared__ int   s_nw;
    __shared__ float s_denres[4];
    int tid = threadIdx.x;
    int r = tid >> 6;
    int d = tid & 63;
    int i = blockIdx.x * 4 + r;

    if (d == 0) {
        float f1 = g_f1[i];
        float thr = -f1;
        int b = bucket_of(thr);
        s_thr[r] = thr;
        s_b[r] = b;
        s_w[r] = __expf((1.0f - ALPHA) * f1);
        s_p0[r] = g_start[b];
        s_p1[r] = g_start[b + 1];
        s_denres[r] = 0.0f;
    }
    __syncthreads();
    if (tid == 0) {
        int m = 0;
#pragma unroll
        for (int q = 0; q < 4; q++) { int cq = s_p1[q] - s_p0[q]; if (cq > m) m = cq; }
        s_nw = (m + 63) >> 6;
    }
    int b = s_b[r];
    int p0 = s_p0[r];
    int cnt = s_p1[r] - p0;
    float w = s_w[r];
    float thr = s_thr[r];
    float pos = g_tp[(b + 1) * DA + d];
    float neg = g_tn[b * DA + d];
    float num = fmaf(w, pos, neg);
    __syncthreads();
    int nw = s_nw;

    for (int wv = 0; wv < nw; wv++) {
        int k = wv * 64 + d;
        float cc = 0.0f;
        int j = 0;
        if (k < cnt) {
            int p = p0 + k;
            float f = g_f2s[p];
            j = g_ord[p];
            cc = (f >= thr) ? w * __expf(f) : __expf(ALPHA * f);
        }
        s_c[r][d] = cc;
        s_j[r][d] = j;
        __syncthreads();
        int lim = cnt - wv * 64;
        if (lim > 64) lim = 64;
        float dres = 0.0f;
        int k2 = 0;
        for (; k2 + 4 <= lim; k2 += 4) {       // MLP=4: batch loads, then FMAs
            float c0 = s_c[r][k2 + 0], c1 = s_c[r][k2 + 1];
            float c2 = s_c[r][k2 + 2], c3 = s_c[r][k2 + 3];
            int   j0 = s_j[r][k2 + 0], j1 = s_j[r][k2 + 1];
            int   j2 = s_j[r][k2 + 2], j3 = s_j[r][k2 + 3];
            float h0 = g_h[j0 * D + d];
            float h1 = g_h[j1 * D + d];
            float h2 = g_h[j2 * D + d];
            float h3 = g_h[j3 * D + d];
            num = fmaf(c0, h0, num);
            num = fmaf(c1, h1, num);
            num = fmaf(c2, h2, num);
            num = fmaf(c3, h3, num);
            dres += (c0 + c1) + (c2 + c3);
        }
        for (; k2 < lim; k2++) {
            float ck = s_c[r][k2];
            num = fmaf(ck, g_h[s_j[r][k2] * D + d], num);
            dres += ck;
        }
        if (d == 0) s_denres[r] += dres;
        __syncthreads();
    }

    if (d == 0) {
        float den = fmaf(w, g_tp[(b + 1) * DA + 64], g_tn[b * DA + 64]) + s_denres[r];
        s_inv[r] = 1.0f / den;
    }
    __syncthreads();
    float v = num * s_inv[r];
    out[i * D + d] = (v > 0.0f) ? v : (__expf(v) - 1.0f);
}

// ---------------- launch ------------------------------------------------------
extern "C" void kernel_launch(void* const* d_in, const int* in_sizes, int n_in,
                              void* d_out, int out_size) {
    const float* x  = (const float*)d_in[0];
    const float* Wt = (const float*)d_in[1];
    const float* a1 = (const float*)d_in[2];
    const float* b1 = (const float*)d_in[3];
    const float* a2 = (const float*)d_in[4];
    const float* b2 = (const float*)d_in[5];
    float* out = (float*)d_out;

    k_hf<<<N / RPB, 128>>>(x, Wt, a1, b1, a2, b2);
    k_mid<<<NCHUNK + 1, 256>>>();
    k_out<<<N / 4, 256>>>(out);
}